// round 10
// baseline (speedup 1.0000x reference)
#include <cuda_runtime.h>
#include <cuda_fp16.h>
#include <cstdint>

#define NMAX 50000
#define EMAX 800000
#define FIN  128
#define FH   128
#define FOUT 64

// ---------------- scratch (device globals; allocation-free) ----------------
__device__ int    g_cnt[NMAX];
__device__ int    g_scan[NMAX];
__device__ int    g_part[256];
__device__ int    g_off[NMAX + 1];
__device__ int    g_cur[NMAX];
__device__ int    g_srcs[EMAX];
__device__ float  g_isd[NMAX];
__device__ float  g_idg[NMAX];
__device__ __half g_h1[(size_t)NMAX * FH];
__device__ float  g_agg1[(size_t)NMAX * FH];
__device__ __half g_h2[(size_t)NMAX * FOUT];

// ---------------------------------------------------------------------------
// CSR build — parallel kernels only (safe to co-schedule with GEMM-1).
// Edge weights are NOT materialized; gathers compute isd[s]*isd[d] on the fly.
// ---------------------------------------------------------------------------
__global__ void k_count(const int* __restrict__ dst, int e) {
    int i = blockIdx.x * blockDim.x + threadIdx.x;
    if (i < e) atomicAdd(&g_cnt[dst[i]], 1);
}

__global__ void k_scan1(int n) {
    __shared__ int sh[256];
    int tid = threadIdx.x;
    int i = blockIdx.x * 256 + tid;
    int v = (i < n) ? g_cnt[i] : 0;
    sh[tid] = v;
    __syncthreads();
#pragma unroll
    for (int d = 1; d < 256; d <<= 1) {
        int t = (tid >= d) ? sh[tid - d] : 0;
        __syncthreads();
        sh[tid] += t;
        __syncthreads();
    }
    if (i < n) g_scan[i] = sh[tid];
    if (tid == 255) g_part[blockIdx.x] = sh[255];
}

// Fused scan2+scan3: each block reduces g_part[0..b-1] itself, then finalizes
// offsets/cursors/degree terms.
__global__ void k_scan23(int n, int e) {
    __shared__ int sh[256];
    const int b = blockIdx.x;
    const int tid = threadIdx.x;

    sh[tid] = (tid < b) ? g_part[tid] : 0;
    __syncthreads();
#pragma unroll
    for (int d = 128; d > 0; d >>= 1) {
        if (tid < d) sh[tid] += sh[tid + d];
        __syncthreads();
    }
    const int blockPrefix = sh[0];

    int i = b * 256 + tid;
    if (i < n) {
        int c = g_cnt[i];
        int excl = g_scan[i] - c + blockPrefix;
        g_off[i] = excl;
        g_cur[i] = excl;
        float deg = (float)c + 1.0f;
        g_isd[i] = rsqrtf(deg);
        g_idg[i] = 1.0f / deg;
    }
    if (i == 0) g_off[n] = e;
}

// Slim fill: index placement only (no weight computation, no isd reads).
__global__ void k_fill(const int* __restrict__ src, const int* __restrict__ dst, int e) {
    int i = blockIdx.x * blockDim.x + threadIdx.x;
    if (i < e) {
        int s = src[i];
        int pos = atomicAdd(&g_cur[dst[i]], 1);
        g_srcs[pos] = s;
    }
}

// ---------------------------------------------------------------------------
// SGEMM (proven tile: BM=128, BN=64, BK=16, 256 thr, 8x4), fp16 epilogue.
// ---------------------------------------------------------------------------
template <int F, bool RELU_A>
__global__ void __launch_bounds__(256)
k_gemm(const float* __restrict__ A, const float* __restrict__ W,
       __half* __restrict__ Hout, int N) {
    constexpr int K = 128, BM = 128, BN = 64, BK = 16;
    __shared__ float As[BK][BM + 4];
    __shared__ float Ws[BK][BN];

    const int tid = threadIdx.x;
    const int rowBase = blockIdx.y * BM;
    const int colBase = blockIdx.x * BN;
    const int ty = tid >> 4;
    const int tx = tid & 15;
    const int wk = tid >> 4;
    const int wn = (tid & 15) * 4;

    float acc[8][4];
#pragma unroll
    for (int i = 0; i < 8; i++)
#pragma unroll
        for (int j = 0; j < 4; j++) acc[i][j] = 0.0f;

    for (int k0 = 0; k0 < K; k0 += BK) {
#pragma unroll
        for (int l = 0; l < 2; l++) {
            int idx = tid + l * 256;
            int row = idx >> 2;
            int kq = (idx & 3) * 4;
            int r = rowBase + row;
            float4 av = make_float4(0.f, 0.f, 0.f, 0.f);
            if (r < N)
                av = *reinterpret_cast<const float4*>(A + (size_t)r * K + k0 + kq);
            if (RELU_A) {
                av.x = fmaxf(av.x, 0.f); av.y = fmaxf(av.y, 0.f);
                av.z = fmaxf(av.z, 0.f); av.w = fmaxf(av.w, 0.f);
            }
            As[kq + 0][row] = av.x;
            As[kq + 1][row] = av.y;
            As[kq + 2][row] = av.z;
            As[kq + 3][row] = av.w;
        }
        *reinterpret_cast<float4*>(&Ws[wk][wn]) =
            *reinterpret_cast<const float4*>(W + (size_t)(k0 + wk) * F + colBase + wn);
        __syncthreads();

#pragma unroll
        for (int k = 0; k < BK; k++) {
            float4 a0 = *reinterpret_cast<const float4*>(&As[k][ty * 8]);
            float4 a1 = *reinterpret_cast<const float4*>(&As[k][ty * 8 + 4]);
            float4 bv = *reinterpret_cast<const float4*>(&Ws[k][tx * 4]);
            float a[8] = {a0.x, a0.y, a0.z, a0.w, a1.x, a1.y, a1.z, a1.w};
            float b[4] = {bv.x, bv.y, bv.z, bv.w};
#pragma unroll
            for (int i = 0; i < 8; i++)
#pragma unroll
                for (int j = 0; j < 4; j++) acc[i][j] = fmaf(a[i], b[j], acc[i][j]);
        }
        __syncthreads();
    }

    const int col = colBase + tx * 4;
    __half2* Hp = reinterpret_cast<__half2*>(Hout);
#pragma unroll
    for (int i = 0; i < 8; i++) {
        int row = rowBase + ty * 8 + i;
        if (row < N) {
            size_t base = ((size_t)row * F + col) >> 1;
            Hp[base + 0] = __floats2half2_rn(acc[i][0], acc[i][1]);
            Hp[base + 1] = __floats2half2_rn(acc[i][2], acc[i][3]);
        }
    }
}

// ---------------------------------------------------------------------------
// CSR gather from fp16 H: warp per node, weights on the fly.
//   Out[d] = sum_{e: dst=d} H[src_e] * isd[src_e]*isd[d] + H[d]*idg[d] + bias
// F=128: LDG.64 (uint2 = 4 halves) per lane per edge.
// ---------------------------------------------------------------------------
__device__ __forceinline__ float2 cvt2(uint32_t u) {
    __half2 h; *reinterpret_cast<uint32_t*>(&h) = u;
    return __half22float2(h);
}

template <int F>
__global__ void __launch_bounds__(256)
k_gather(const __half* __restrict__ H, const float* __restrict__ bias,
         float* __restrict__ Out, int N) {
    int gw = (blockIdx.x * blockDim.x + threadIdx.x) >> 5;
    int lane = threadIdx.x & 31;
    if (gw >= N) return;
    const int beg = g_off[gw];
    const int end = g_off[gw + 1];
    const float isd_d = g_isd[gw];

    if (F == 128) {
        const uint2* __restrict__ Hp = reinterpret_cast<const uint2*>(H);  // 32 uint2/row
        const size_t rbase = (size_t)gw * 32 + lane;
        float idg = g_idg[gw];
        uint2 hu = Hp[rbase];
        float2 h0 = cvt2(hu.x), h1 = cvt2(hu.y);
        float4 bv = *reinterpret_cast<const float4*>(bias + lane * 4);
        float4 acc = make_float4(fmaf(h0.x, idg, bv.x), fmaf(h0.y, idg, bv.y),
                                 fmaf(h1.x, idg, bv.z), fmaf(h1.y, idg, bv.w));
        int j = beg;
        for (; j + 1 < end; j += 2) {
            int s0 = g_srcs[j], s1 = g_srcs[j + 1];
            float w0 = isd_d * g_isd[s0];
            float w1 = isd_d * g_isd[s1];
            uint2 u0 = Hp[(size_t)s0 * 32 + lane];
            uint2 u1 = Hp[(size_t)s1 * 32 + lane];
            float2 a0 = cvt2(u0.x), b0 = cvt2(u0.y);
            float2 a1 = cvt2(u1.x), b1 = cvt2(u1.y);
            acc.x = fmaf(a0.x, w0, acc.x); acc.y = fmaf(a0.y, w0, acc.y);
            acc.z = fmaf(b0.x, w0, acc.z); acc.w = fmaf(b0.y, w0, acc.w);
            acc.x = fmaf(a1.x, w1, acc.x); acc.y = fmaf(a1.y, w1, acc.y);
            acc.z = fmaf(b1.x, w1, acc.z); acc.w = fmaf(b1.y, w1, acc.w);
        }
        if (j < end) {
            int s = g_srcs[j];
            float w = isd_d * g_isd[s];
            uint2 u = Hp[(size_t)s * 32 + lane];
            float2 a = cvt2(u.x), b = cvt2(u.y);
            acc.x = fmaf(a.x, w, acc.x); acc.y = fmaf(a.y, w, acc.y);
            acc.z = fmaf(b.x, w, acc.z); acc.w = fmaf(b.y, w, acc.w);
        }
        *reinterpret_cast<float4*>(Out + (size_t)gw * 128 + lane * 4) = acc;
    } else {
        const uint32_t* __restrict__ Hp = reinterpret_cast<const uint32_t*>(H); // 32 half2/row
        const size_t rbase = (size_t)gw * 32 + lane;
        float idg = g_idg[gw];
        float2 hv = cvt2(Hp[rbase]);
        float2 bv = *reinterpret_cast<const float2*>(bias + lane * 2);
        float2 acc = make_float2(fmaf(hv.x, idg, bv.x), fmaf(hv.y, idg, bv.y));
        int j = beg;
        for (; j + 1 < end; j += 2) {
            int s0 = g_srcs[j], s1 = g_srcs[j + 1];
            float w0 = isd_d * g_isd[s0];
            float w1 = isd_d * g_isd[s1];
            float2 v0 = cvt2(Hp[(size_t)s0 * 32 + lane]);
            float2 v1 = cvt2(Hp[(size_t)s1 * 32 + lane]);
            acc.x = fmaf(v0.x, w0, acc.x); acc.y = fmaf(v0.y, w0, acc.y);
            acc.x = fmaf(v1.x, w1, acc.x); acc.y = fmaf(v1.y, w1, acc.y);
        }
        if (j < end) {
            int s = g_srcs[j];
            float w = isd_d * g_isd[s];
            float2 v = cvt2(Hp[(size_t)s * 32 + lane]);
            acc.x = fmaf(v.x, w, acc.x); acc.y = fmaf(v.y, w, acc.y);
        }
        *reinterpret_cast<float2*>(Out + (size_t)gw * 64 + lane * 2) = acc;
    }
}

// ---------------------------------------------------------------------------
// Launch: build overlapped with GEMM-1.
// ---------------------------------------------------------------------------
extern "C" void kernel_launch(void* const* d_in, const int* in_sizes, int n_in,
                              void* d_out, int out_size) {
    const float* x  = (const float*)d_in[0];
    const int* eidx = (const int*)d_in[1];
    const float* W1 = (const float*)d_in[2];
    const float* b1 = (const float*)d_in[3];
    const float* W2 = (const float*)d_in[4];
    const float* b2 = (const float*)d_in[5];
    float* out = (float*)d_out;

    const int N = in_sizes[0] / FIN;   // 50000
    const int E = in_sizes[1] / 2;     // 800000
    const int* src = eidx;
    const int* dst = eidx + E;

    static cudaStream_t s2 = nullptr;
    static cudaEvent_t evFork = nullptr, evBuild = nullptr;
    if (!s2) {
        cudaStreamCreateWithFlags(&s2, cudaStreamNonBlocking);
        cudaEventCreateWithFlags(&evFork, cudaEventDisableTiming);
        cudaEventCreateWithFlags(&evBuild, cudaEventDisableTiming);
    }

    __half *h1, *h2;
    float *agg1;
    void *cntp;
    cudaGetSymbolAddress((void**)&h1, g_h1);
    cudaGetSymbolAddress((void**)&agg1, g_agg1);
    cudaGetSymbolAddress((void**)&h2, g_h2);
    cudaGetSymbolAddress(&cntp, g_cnt);

    const int nScanBlocks = (N + 255) / 256;
    const int rowBlocks = (N + 127) / 128;
    const int gatherBlocks = (N * 32 + 255) / 256;

    // Fork: CSR build on s2, GEMM-1 on main stream.
    cudaEventRecord(evFork, 0);
    cudaStreamWaitEvent(s2, evFork, 0);

    cudaMemsetAsync(cntp, 0, (size_t)N * sizeof(int), s2);
    k_count<<<(E + 255) / 256, 256, 0, s2>>>(dst, E);
    k_scan1<<<nScanBlocks, 256, 0, s2>>>(N);
    k_scan23<<<nScanBlocks, 256, 0, s2>>>(N, E);
    k_fill<<<(E + 255) / 256, 256, 0, s2>>>(src, dst, E);
    cudaEventRecord(evBuild, s2);

    // GEMM-1 concurrently on main stream.
    {
        dim3 grid(FH / 64, rowBlocks);
        k_gemm<FH, false><<<grid, 256>>>(x, W1, h1, N);
    }

    // Join, then serial tail.
    cudaStreamWaitEvent(0, evBuild, 0);
    k_gather<FH><<<gatherBlocks, 256>>>(h1, b1, agg1, N);
    {
        dim3 grid(FOUT / 64, rowBlocks);
        k_gemm<FOUT, true><<<grid, 256>>>(agg1, W2, h2, N);
    }
    k_gather<FOUT><<<gatherBlocks, 256>>>(h2, b2, out, N);
}